// round 15
// baseline (speedup 1.0000x reference)
#include <cuda_runtime.h>
#include <cuda_fp16.h>
#include <cstdint>

#define N_EDGES_C 500000
#define N1 448
#define N2 256
#define N3 128
#define KY 416
#define SA_Y 424
#define SA2 456
#define SA3 264
#define SO3 136
#define SBS32 40
#define SBS64 72
#define BS32BYTES 35840
#define BS64BYTES 36864
#define W3CHUNK   18432

__device__ __half g_zc[(size_t)20000 * KY];
__device__ __half g_w1c[(size_t)26 * 17920];
__device__ __half g_w2c[(size_t)7 * 18432];
__device__ __half g_w3c[(size_t)4 * 9216];
__device__ __half g_ytop[(size_t)20000 * N1];
__device__ __half g_ybot[(size_t)20000 * N1];
__device__ int g_idx64;

__device__ __forceinline__ uint32_t smem_u32(const void* p) {
    uint32_t a;
    asm("{ .reg .u64 t; cvta.to.shared.u64 t, %1; cvt.u32.u64 %0, t; }" : "=r"(a) : "l"(p));
    return a;
}
#define LDSM4(r0, r1, r2, r3, a) \
    asm volatile("ldmatrix.sync.aligned.m8n8.x4.shared.b16 {%0,%1,%2,%3}, [%4];" \
                 : "=r"(r0), "=r"(r1), "=r"(r2), "=r"(r3) : "r"(a))
#define LDSM2(r0, r1, a) \
    asm volatile("ldmatrix.sync.aligned.m8n8.x2.shared.b16 {%0,%1}, [%2];" \
                 : "=r"(r0), "=r"(r1) : "r"(a))
#define HMMA(d, a0, a1, a2, a3, b0, b1) \
    asm volatile("mma.sync.aligned.m16n8k16.row.col.f32.f16.f16.f32 " \
                 "{%0,%1,%2,%3}, {%4,%5,%6,%7}, {%8,%9}, {%0,%1,%2,%3};" \
                 : "+f"((d)[0]), "+f"((d)[1]), "+f"((d)[2]), "+f"((d)[3]) \
                 : "r"(a0), "r"(a1), "r"(a2), "r"(a3), "r"(b0), "r"(b1))
#define CPA16(dst, src) \
    asm volatile("cp.async.ca.shared.global [%0], [%1], 16;" :: "r"(dst), "l"(src))
#define CPA_COMMIT() asm volatile("cp.async.commit_group;" ::: "memory")
#define CPA_WAIT(n)  asm volatile("cp.async.wait_group %0;" :: "n"(n) : "memory")
#define MB_INIT(a, c) asm volatile("mbarrier.init.shared.b64 [%0], %1;" :: "r"((uint32_t)(a)), "r"((uint32_t)(c)) : "memory")
#define MB_WAIT(a, par) do { \
    uint32_t _m = (uint32_t)(a), _p = (uint32_t)(par), _d; \
    asm volatile("{\n\t.reg .pred p;\n\tmbarrier.try_wait.parity.acquire.cta.shared::cta.b64 p, [%1], %2;\n\tselp.b32 %0, 1, 0, p;\n\t}" \
                 : "=r"(_d) : "r"(_m), "r"(_p) : "memory"); \
    if (!_d) asm volatile("{\n\t.reg .pred P1;\n\tWL_%=:\n\tmbarrier.try_wait.parity.acquire.cta.shared::cta.b64 P1, [%0], %1, 0x989680;\n\t@P1 bra.uni WD_%=;\n\tbra.uni WL_%=;\n\tWD_%=:\n\t}" \
                 :: "r"(_m), "r"(_p) : "memory"); \
} while (0)

__device__ __forceinline__ void bulk_issue(uint32_t aB, uint32_t bufbytes,
                                           const __half* src, uint32_t bytes,
                                           uint32_t mb0, uint32_t mb1, int& icnt, int tid) {
    int buf = icnt & 1;
    if (tid == 0) {
        uint32_t mb = buf ? mb1 : mb0;
        uint32_t dst = aB + buf * bufbytes;
        asm volatile("mbarrier.arrive.expect_tx.shared.b64 _, [%0], %1;"
                     :: "r"(mb), "r"(bytes) : "memory");
        asm volatile("cp.async.bulk.shared::cluster.global.mbarrier::complete_tx::bytes [%0], [%1], %2, [%3];"
                     :: "r"(dst), "l"(src), "r"(bytes), "r"(mb) : "memory");
    }
    icnt++;
}
__device__ __forceinline__ int bulk_wait(uint32_t mb0, uint32_t mb1, int& wcnt, int* ph) {
    int buf = wcnt & 1;
    MB_WAIT(buf ? mb1 : mb0, ph[buf]);
    ph[buf] ^= 1;
    wcnt++;
    return buf;
}

__global__ void detect_idx(const int* ei) {
    int z = 0;
    for (int i = 0; i < 64; i++) z |= ei[2 * i + 1];
    g_idx64 = (z == 0) ? 1 : 0;
}

// ---------- P1: node MLP + zc ----------
__global__ void __launch_bounds__(256) prep_nodes(
    const float* __restrict__ z, const float* __restrict__ cell,
    const float* __restrict__ esm,
    const float* __restrict__ w1, const float* __restrict__ b1,
    const float* __restrict__ w2, const float* __restrict__ b2,
    const float* __restrict__ w3, const float* __restrict__ b3) {
    __shared__ float sc[4][4], h1[4][64], h2[4][32], m16[4][16];
    const int sub = threadIdx.x >> 6, t = threadIdx.x & 63;
    const int i = blockIdx.x * 4 + sub;
    if (t < 4) sc[sub][t] = cell[i * 4 + t];
    __syncthreads();
    {
        float s = b1[t];
        for (int j = 0; j < 4; j++) s += sc[sub][j] * w1[j * 64 + t];
        h1[sub][t] = fmaxf(s, 0.f);
    }
    __syncthreads();
    if (t < 32) {
        float s = b2[t];
        for (int j = 0; j < 64; j++) s += h1[sub][j] * w2[j * 32 + t];
        h2[sub][t] = fmaxf(s, 0.f);
    }
    __syncthreads();
    if (t < 16) {
        float s = b3[t];
        for (int j = 0; j < 32; j++) s += h2[sub][j] * w3[j * 16 + t];
        m16[sub][t] = s;
    }
    __syncthreads();
    for (int col = t; col < KY; col += 64) {
        float v = 0.f;
        if (col < 64)       v = z[i * 64 + col];
        else if (col < 80)  v = m16[sub][col - 64];
        else if (col < 400) v = esm[i * 320 + (col - 80)];
        g_zc[(size_t)i * KY + col] = __float2half_rn(v);
    }
}

// ---------- P2: weights -> chunk-contiguous pre-strided f16 ----------
__global__ void prep_weights(const float* __restrict__ fw1, const float* __restrict__ fw2,
                             const float* __restrict__ fw3) {
    int i = blockIdx.x * blockDim.x + threadIdx.x;
    const int T1 = 26 * 17920, T2 = 7 * 18432, T3 = 4 * 9216;
    if (i < T1) {
        int chunk = i / 17920, r = i % 17920;
        int h = chunk / 13, c = chunk % 13;
        int n = r / 40, kk = r % 40;
        int k = c * 32 + kk;
        float v = 0.f;
        if (kk < 32 && n < 400 && k < 400) v = fw1[(h * 400 + k) * 400 + n];
        g_w1c[i] = __float2half_rn(v);
    } else if (i < T1 + T2) {
        int j = i - T1;
        int c = j / 18432, r = j % 18432;
        int n = r / 72, kk = r % 72;
        int k = c * 64 + kk;
        float v = 0.f;
        if (kk < 64 && n < 200 && k < 400) v = fw2[k * 200 + n];
        g_w2c[j] = __float2half_rn(v);
    } else if (i < T1 + T2 + T3) {
        int j = i - T1 - T2;
        int c = j / 9216, r = j % 9216;
        int n = r / 72, kk = r % 72;
        int k = c * 64 + kk;
        float v = 0.f;
        if (kk < 64 && n < 100 && k < 200) v = fw3[k * 100 + n];
        g_w3c[j] = __float2half_rn(v);
    }
}

// ---------- gemm32b (prep_y) ----------
template <int NTILES, int NCH>
__device__ __forceinline__ void gemm32b(const __half* __restrict__ Wc,
                                        const __half* __restrict__ Wnextc, uint32_t nextbytes,
                                        uint32_t aA, uint32_t aB, int SA, float* acc,
                                        uint32_t mb0, uint32_t mb1, int& icnt, int& wcnt, int* ph,
                                        int wm, int wn, int lane, int tid) {
#pragma unroll
    for (int i = 0; i < 2 * NTILES * 4; i++) acc[i] = 0.f;
    const uint32_t brow = wn * (NTILES * 8) + (lane & 7) + ((lane >> 4) << 3);
#pragma unroll 1
    for (int c = 0; c < NCH; c++) {
        if (c + 1 < NCH)
            bulk_issue(aB, BS32BYTES, Wc + (size_t)(c + 1) * 17920, BS32BYTES, mb0, mb1, icnt, tid);
        else if (Wnextc)
            bulk_issue(aB, BS32BYTES, Wnextc, nextbytes, mb0, mb1, icnt, tid);
        const int buf = bulk_wait(mb0, mb1, wcnt, ph);
        const uint32_t bbase = aB + buf * BS32BYTES;
#pragma unroll
        for (int s = 0; s < 2; s++) {
            uint32_t aaddr = aA + (((wm * 32 + (lane & 15)) * SA + c * 32 + s * 16 + ((lane >> 4) << 3)) << 1);
            uint32_t a0, a1, a2, a3, e0, e1, e2, e3;
            LDSM4(a0, a1, a2, a3, aaddr);
            LDSM4(e0, e1, e2, e3, aaddr + 16 * SA * 2);
            uint32_t baddr = bbase + ((brow * SBS32 + s * 16 + (((lane >> 3) & 1) << 3)) << 1);
#pragma unroll
            for (int g = 0; g < NTILES / 2; g++) {
                uint32_t b0, b1, b2, b3;
                LDSM4(b0, b1, b2, b3, baddr + g * (16 * SBS32 * 2));
                HMMA(acc + (2 * g) * 4, a0, a1, a2, a3, b0, b1);
                HMMA(acc + (2 * g + 1) * 4, a0, a1, a2, a3, b2, b3);
                HMMA(acc + (NTILES + 2 * g) * 4, e0, e1, e2, e3, b0, b1);
                HMMA(acc + (NTILES + 2 * g + 1) * 4, e0, e1, e2, e3, b2, b3);
            }
            if (NTILES & 1) {
                uint32_t b0, b1;
                LDSM2(b0, b1, baddr + (NTILES / 2) * (16 * SBS32 * 2));
                HMMA(acc + (NTILES - 1) * 4, a0, a1, a2, a3, b0, b1);
                HMMA(acc + (2 * NTILES - 1) * 4, e0, e1, e2, e3, b0, b1);
            }
        }
        __syncthreads();
    }
}

// ---------- prep_y ----------
#define SMY_MB 0
#define SMY_A  64
#define SMY_B  (64 + 54272)
#define SMEM_Y (SMY_B + 2 * BS32BYTES)

__global__ void __launch_bounds__(512) prep_y_kernel() {
    extern __shared__ char smem[];
    const uint32_t mb0 = smem_u32(smem + SMY_MB);
    const uint32_t mb1 = mb0 + 8;
    const uint32_t aA = smem_u32(smem + SMY_A);
    const uint32_t aB = smem_u32(smem + SMY_B);
    const int tid = threadIdx.x;
    const int wid = tid >> 5, lane = tid & 31;
    const int wm = wid & 1, wn = wid >> 1;
    const int base = blockIdx.x * 64;

    if (tid == 0) { MB_INIT(mb0, 1); MB_INIT(mb1, 1); }
    __syncthreads();

    int icnt = 0, wcnt = 0, ph[2] = {0, 0};
    bulk_issue(aB, BS32BYTES, g_w1c, BS32BYTES, mb0, mb1, icnt, tid);

    for (int i = tid; i < 64 * 52; i += 512) {
        int r = i / 52, u = i % 52;
        int grow = base + r; if (grow > 19999) grow = 19999;
        CPA16(aA + ((r * SA_Y + u * 8) << 1), g_zc + (size_t)grow * KY + u * 8);
    }
    CPA_COMMIT(); CPA_WAIT(0);
    __syncthreads();

    float acc[56];
    gemm32b<7, 13>(g_w1c, g_w1c + (size_t)13 * 17920, BS32BYTES,
                   aA, aB, SA_Y, acc, mb0, mb1, icnt, wcnt, ph, wm, wn, lane, tid);
#pragma unroll
    for (int mt = 0; mt < 2; mt++) {
        int r0 = base + wm * 32 + mt * 16 + (lane >> 2);
#pragma unroll
        for (int nt = 0; nt < 7; nt++) {
            int c = wn * 56 + nt * 8 + (lane & 3) * 2;
            float* d = acc + (mt * 7 + nt) * 4;
            if (r0 < 20000) *(__half2*)(g_ytop + (size_t)r0 * N1 + c) = __floats2half2_rn(d[0], d[1]);
            if (r0 + 8 < 20000) *(__half2*)(g_ytop + (size_t)(r0 + 8) * N1 + c) = __floats2half2_rn(d[2], d[3]);
        }
    }
    gemm32b<7, 13>(g_w1c + (size_t)13 * 17920, nullptr, 0,
                   aA, aB, SA_Y, acc, mb0, mb1, icnt, wcnt, ph, wm, wn, lane, tid);
#pragma unroll
    for (int mt = 0; mt < 2; mt++) {
        int r0 = base + wm * 32 + mt * 16 + (lane >> 2);
#pragma unroll
        for (int nt = 0; nt < 7; nt++) {
            int c = wn * 56 + nt * 8 + (lane & 3) * 2;
            float* d = acc + (mt * 7 + nt) * 4;
            if (r0 < 20000) *(__half2*)(g_ybot + (size_t)r0 * N1 + c) = __floats2half2_rn(d[0], d[1]);
            if (r0 + 8 < 20000) *(__half2*)(g_ybot + (size_t)(r0 + 8) * N1 + c) = __floats2half2_rn(d[2], d[3]);
        }
    }
}

// ---------- gemm64b (FC3) ----------
template <int NTILES, int NCH>
__device__ __forceinline__ void gemm64b(const __half* __restrict__ Wc, uint32_t chunkbytes,
                                        uint32_t aA, uint32_t aB, int SA, float* acc,
                                        uint32_t mb0, uint32_t mb1, int& icnt, int& wcnt, int* ph,
                                        int wm, int wn, int lane, int tid) {
#pragma unroll
    for (int i = 0; i < 2 * NTILES * 4; i++) acc[i] = 0.f;
    const uint32_t brow = wn * (NTILES * 8) + (lane & 7) + ((lane >> 4) << 3);
#pragma unroll 1
    for (int c = 0; c < NCH; c++) {
        if (c + 1 < NCH)
            bulk_issue(aB, BS64BYTES, Wc + (size_t)(c + 1) * (chunkbytes / 2), chunkbytes, mb0, mb1, icnt, tid);
        const int buf = bulk_wait(mb0, mb1, wcnt, ph);
        const uint32_t bbase = aB + buf * BS64BYTES;
#pragma unroll
        for (int s = 0; s < 4; s++) {
            uint32_t aaddr = aA + (((wm * 32 + (lane & 15)) * SA + c * 64 + s * 16 + ((lane >> 4) << 3)) << 1);
            uint32_t a0, a1, a2, a3, e0, e1, e2, e3;
            LDSM4(a0, a1, a2, a3, aaddr);
            LDSM4(e0, e1, e2, e3, aaddr + 16 * SA * 2);
            uint32_t baddr = bbase + ((brow * SBS64 + s * 16 + (((lane >> 3) & 1) << 3)) << 1);
#pragma unroll
            for (int g = 0; g < NTILES / 2; g++) {
                uint32_t b0, b1, b2, b3;
                LDSM4(b0, b1, b2, b3, baddr + g * (16 * SBS64 * 2));
                HMMA(acc + (2 * g) * 4, a0, a1, a2, a3, b0, b1);
                HMMA(acc + (2 * g + 1) * 4, a0, a1, a2, a3, b2, b3);
                HMMA(acc + (NTILES + 2 * g) * 4, e0, e1, e2, e3, b0, b1);
                HMMA(acc + (NTILES + 2 * g + 1) * 4, e0, e1, e2, e3, b2, b3);
            }
        }
        __syncthreads();
    }
}

template <int NTILES>
__device__ __forceinline__ void epi(float* acc, __half* A, int SO, const float* bias,
                                    int wm, int wn, int lane) {
#pragma unroll
    for (int mt = 0; mt < 2; mt++) {
        int r0 = wm * 32 + mt * 16 + (lane >> 2);
#pragma unroll
        for (int nt = 0; nt < NTILES; nt++) {
            int c = wn * (NTILES * 8) + nt * 8 + (lane & 3) * 2;
            float* d = acc + (mt * NTILES + nt) * 4;
            *(__half2*)(A + r0 * SO + c) =
                __floats2half2_rn(fmaxf(d[0] + bias[c], 0.f), fmaxf(d[1] + bias[c + 1], 0.f));
            *(__half2*)(A + (r0 + 8) * SO + c) =
                __floats2half2_rn(fmaxf(d[2] + bias[c], 0.f), fmaxf(d[3] + bias[c + 1], 0.f));
        }
    }
}

// ---------- edge kernel: M=128, 512 thr, combine pipelined into FC2 ----------
#define SME_MB   0
#define SME_NS   64
#define SME_ND   576
#define SME_BIAS 1088
#define SME_A    5056
#define SME_B    121792
#define SMEM_E   (SME_B + 2 * BS64BYTES)

__global__ void __launch_bounds__(512) edge_mlp_kernel(
    const void* __restrict__ eidx_raw, const float* __restrict__ fb1,
    const float* __restrict__ fb2, const float* __restrict__ fb3,
    const float* __restrict__ fw4, const float* __restrict__ fb4,
    float* __restrict__ out) {
    extern __shared__ char smem[];
    const uint32_t mb0 = smem_u32(smem + SME_MB);
    const uint32_t mb1 = mb0 + 8;
    int* ns = (int*)(smem + SME_NS);
    int* nd = (int*)(smem + SME_ND);
    float* bias = (float*)(smem + SME_BIAS);
    __half* A = (__half*)(smem + SME_A);
    const uint32_t aA = smem_u32(A);
    const uint32_t aB = smem_u32(smem + SME_B);

    const int tid = threadIdx.x;
    const int wid = tid >> 5, lane = tid & 31;
    const int wm = wid & 3, wn = wid >> 2;
    const long long base = (long long)blockIdx.x * 128;

    if (tid == 0) { MB_INIT(mb0, 1); MB_INIT(mb1, 1); }
    __syncthreads();

    int icnt = 0, wcnt = 0, ph[2] = {0, 0};
    bulk_issue(aB, BS64BYTES, g_w2c, BS64BYTES, mb0, mb1, icnt, tid);

    for (int i = tid; i < 448; i += 512) bias[i] = (i < 400) ? fb1[i] : 0.f;
    if (tid < 256) bias[448 + tid] = (tid < 200) ? fb2[tid] : 0.f;
    else if (tid < 384) { int i = tid - 256; bias[704 + i] = (i < 100) ? fb3[i] : 0.f; }
    else { int i = tid - 384; bias[832 + i] = (i < 100) ? fw4[i] : 0.f; }
    if (tid == 0) bias[960] = fb4[0];

    if (tid < 128) {
        long long e = base + tid;
        if (e >= N_EDGES_C) e = N_EDGES_C - 1;
        if (g_idx64) {
            const long long* ei = (const long long*)eidx_raw;
            ns[tid] = (int)ei[e]; nd[tid] = (int)ei[N_EDGES_C + e];
        } else {
            const int* ei = (const int*)eidx_raw;
            ns[tid] = ei[e]; nd[tid] = ei[N_EDGES_C + e];
        }
    }
    __syncthreads();

    // per-thread combine slots for one 64-col chunk: i0 = tid, i1 = tid + 512 (of 1024)
    const int cr0 = tid >> 3, cu0 = tid & 7;          // row, ugroup of slot 0
    const int cr1 = (tid + 512) >> 3, cu1 = tid & 7;  // slot 1 (same u pattern)

#define COMBINE_LOAD(cc, tv0, bv0, tv1, bv1) do { \
    int col0 = (cc) * 64 + cu0 * 8; \
    tv0 = *(const uint4*)(g_ytop + (size_t)ns[cr0] * N1 + col0); \
    bv0 = *(const uint4*)(g_ybot + (size_t)nd[cr0] * N1 + col0); \
    tv1 = *(const uint4*)(g_ytop + (size_t)ns[cr1] * N1 + col0); \
    bv1 = *(const uint4*)(g_ybot + (size_t)nd[cr1] * N1 + col0); \
} while (0)

#define COMBINE_STORE(cc, tv, bv, rr) do { \
    int col0 = (cc) * 64 + cu0 * 8; \
    const __half2* tp = (const __half2*)&(tv); \
    const __half2* bp = (const __half2*)&(bv); \
    const float* bb = bias + col0; \
    __half2 h[4]; \
    for (int j = 0; j < 4; j++) { \
        float2 t2 = __half22float2(tp[j]); \
        float2 b2 = __half22float2(bp[j]); \
        h[j] = __floats2half2_rn(fmaxf(t2.x + b2.x + bb[2 * j], 0.f), \
                                 fmaxf(t2.y + b2.y + bb[2 * j + 1], 0.f)); \
    } \
    *(uint4*)(A + (rr) * SA2 + col0) = *(uint4*)h; \
} while (0)

    // combine chunk 0 (exposed)
    {
        uint4 t0, b0v, t1, b1v;
        COMBINE_LOAD(0, t0, b0v, t1, b1v);
        COMBINE_STORE(0, t0, b0v, cr0);
        COMBINE_STORE(0, t1, b1v, cr1);
    }
    __syncthreads();

    float acc[64];
    // ===== FC2 with pipelined combine =====
    {
#pragma unroll
        for (int i = 0; i < 64; i++) acc[i] = 0.f;
        const uint32_t brow = wn * 64 + (lane & 7) + ((lane >> 4) << 3);
#pragma unroll 1
        for (int c = 0; c < 7; c++) {
            if (c + 1 < 7)
                bulk_issue(aB, BS64BYTES, g_w2c + (size_t)(c + 1) * 18432, BS64BYTES, mb0, mb1, icnt, tid);
            else
                bulk_issue(aB, BS64BYTES, g_w3c, W3CHUNK, mb0, mb1, icnt, tid);
            // issue next combine-chunk loads (latency hidden under MMA sweep)
            uint4 t0, b0v, t1, b1v;
            if (c + 1 < 7) COMBINE_LOAD(c + 1, t0, b0v, t1, b1v);
            const int buf = bulk_wait(mb0, mb1, wcnt, ph);
            const uint32_t bbase = aB + buf * BS64BYTES;
#pragma unroll
            for (int s = 0; s < 4; s++) {
                uint32_t aaddr = aA + (((wm * 32 + (lane & 15)) * SA2 + c * 64 + s * 16 + ((lane >> 4) << 3)) << 1);
                uint32_t a0, a1, a2, a3, e0, e1, e2, e3;
                LDSM4(a0, a1, a2, a3, aaddr);
                LDSM4(e0, e1, e2, e3, aaddr + 16 * SA2 * 2);
                uint32_t baddr = bbase + ((brow * SBS64 + s * 16 + (((lane >> 3) & 1) << 3)) << 1);
#pragma unroll
                for (int g = 0; g < 4; g++) {
                    uint32_t b0, b1, b2, b3;
                    LDSM4(b0, b1, b2, b3, baddr + g * (16 * SBS64 * 2));
                    HMMA(acc + (2 * g) * 4, a0, a1, a2, a3, b0, b1);
                    HMMA(acc + (2 * g + 1) * 4, a0, a1, a2, a3, b2, b3);
                    HMMA(acc + (8 + 2 * g) * 4, e0, e1, e2, e3, b0, b1);
                    HMMA(acc + (8 + 2 * g + 1) * 4, e0, e1, e2, e3, b2, b3);
                }
            }
            if (c + 1 < 7) {
                COMBINE_STORE(c + 1, t0, b0v, cr0);
                COMBINE_STORE(c + 1, t1, b1v, cr1);
            }
            __syncthreads();
        }
    }
    epi<8>(acc, A, SA3, bias + 448, wm, wn, lane);
    __syncthreads();
    // ===== FC3 =====
    gemm64b<4, 4>(g_w3c, W3CHUNK, aA, aB, SA3, acc, mb0, mb1, icnt, wcnt, ph, wm, wn, lane, tid);
    epi<4>(acc, A, SO3, bias + 704, wm, wn, lane);
    __syncthreads();

    // head
#pragma unroll 1
    for (int q = 0; q < 8; q++) {
        int r = wid * 8 + q;
        const __half* ar = A + r * SO3;
        float s = 0.f;
#pragma unroll
        for (int j = 0; j < 4; j++) {
            int c = lane + j * 32;
            if (c < 100) s += __half2float(ar[c]) * bias[832 + c];
        }
#pragma unroll
        for (int o = 16; o; o >>= 1) s += __shfl_xor_sync(~0u, s, o);
        if (lane == 0) {
            long long e = base + r;
            if (e < N_EDGES_C) out[e] = s + bias[960];
        }
    }
}

extern "C" void kernel_launch(void* const* d_in, const int* in_sizes, int n_in,
                              void* d_out, int out_size) {
    static const int EXP[18] = {1280000, 1000000, 80000, 6400000, 256, 64, 2048, 32, 512, 16,
                                320000, 400, 80000, 200, 20000, 100, 100, 1};
    const void* p[18];
    bool used[32] = {false};
    for (int j = 0; j < 18; j++) {
        p[j] = (j < n_in) ? d_in[j] : nullptr;
        for (int i = 0; i < n_in && i < 32; i++) {
            if (!used[i] && in_sizes[i] == EXP[j]) { p[j] = d_in[i]; used[i] = true; break; }
        }
    }
    const float* z    = (const float*)p[0];
    const void*  ei   = p[1];
    const float* cell = (const float*)p[2];
    const float* esm  = (const float*)p[3];
    const float* mw1 = (const float*)p[4];
    const float* mb1 = (const float*)p[5];
    const float* mw2 = (const float*)p[6];
    const float* mb2 = (const float*)p[7];
    const float* mw3 = (const float*)p[8];
    const float* mb3 = (const float*)p[9];
    const float* f1w = (const float*)p[10];
    const float* f1b = (const float*)p[11];
    const float* f2w = (const float*)p[12];
    const float* f2b = (const float*)p[13];
    const float* f3w = (const float*)p[14];
    const float* f3b = (const float*)p[15];
    const float* f4w = (const float*)p[16];
    const float* f4b = (const float*)p[17];
    float* out = (float*)d_out;

    cudaFuncSetAttribute(prep_y_kernel, cudaFuncAttributeMaxDynamicSharedMemorySize, SMEM_Y);
    cudaFuncSetAttribute(edge_mlp_kernel, cudaFuncAttributeMaxDynamicSharedMemorySize, SMEM_E);

    detect_idx<<<1, 1>>>((const int*)ei);
    prep_nodes<<<5000, 256>>>(z, cell, esm, mw1, mb1, mw2, mb2, mw3, mb3);
    const int WT = 26 * 17920 + 7 * 18432 + 4 * 9216;
    prep_weights<<<(WT + 255) / 256, 256>>>(f1w, f2w, f3w);
    prep_y_kernel<<<313, 512, SMEM_Y>>>();
    edge_mlp_kernel<<<(N_EDGES_C + 127) / 128, 512, SMEM_E>>>(
        ei, f1b, f2b, f3b, f4w, f4b, out);
}

// round 16
// speedup vs baseline: 1.3146x; 1.3146x over previous
#include <cuda_runtime.h>
#include <cuda_fp16.h>
#include <cstdint>

#define N_EDGES_C 500000
#define N1 448
#define KY 416
#define SA_Y 424
#define SBS32 40
#define BS32BYTES 35840

__device__ __half g_zc[(size_t)20000 * KY];
__device__ __half g_w1c[(size_t)26 * 17920];
__device__ __half g_w2s[(size_t)7 * 16384];   // W2 SW128 chunk images: [c][4 nb x 64r x 128B]
__device__ __half g_w3s[(size_t)4 * 8192];    // W3 SW128 chunk images: [c][2 nb x 64r x 128B]
__device__ __half g_w2c[(size_t)7 * 18432];   // linear (fallback only)
__device__ __half g_w3c[(size_t)4 * 9216];
__device__ __half g_ytop[(size_t)20000 * N1];
__device__ __half g_ybot[(size_t)20000 * N1];
__device__ int g_idx64;

#define SWZ(o) ((o) ^ (((o) >> 3) & 0x70))
__device__ __forceinline__ uint32_t smem_u32(const void* p) {
    uint32_t a;
    asm("{ .reg .u64 t; cvta.to.shared.u64 t, %1; cvt.u32.u64 %0, t; }" : "=r"(a) : "l"(p));
    return a;
}
#define LDSM4(r0, r1, r2, r3, a) \
    asm volatile("ldmatrix.sync.aligned.m8n8.x4.shared.b16 {%0,%1,%2,%3}, [%4];" \
                 : "=r"(r0), "=r"(r1), "=r"(r2), "=r"(r3) : "r"(a))
#define LDSM2(r0, r1, a) \
    asm volatile("ldmatrix.sync.aligned.m8n8.x2.shared.b16 {%0,%1}, [%2];" \
                 : "=r"(r0), "=r"(r1) : "r"(a))
#define HMMA(d, a0, a1, a2, a3, b0, b1) \
    asm volatile("mma.sync.aligned.m16n8k16.row.col.f32.f16.f16.f32 " \
                 "{%0,%1,%2,%3}, {%4,%5,%6,%7}, {%8,%9}, {%0,%1,%2,%3};" \
                 : "+f"((d)[0]), "+f"((d)[1]), "+f"((d)[2]), "+f"((d)[3]) \
                 : "r"(a0), "r"(a1), "r"(a2), "r"(a3), "r"(b0), "r"(b1))
#define CPA16(dst, src) \
    asm volatile("cp.async.ca.shared.global [%0], [%1], 16;" :: "r"(dst), "l"(src))
#define CPA_COMMIT() asm volatile("cp.async.commit_group;" ::: "memory")
#define CPA_WAIT(n)  asm volatile("cp.async.wait_group %0;" :: "n"(n) : "memory")
#define MB_INIT(a, c) asm volatile("mbarrier.init.shared.b64 [%0], %1;" :: "r"((uint32_t)(a)), "r"((uint32_t)(c)) : "memory")
#define MB_ARRIVE(a) asm volatile("mbarrier.arrive.shared.b64 _, [%0];" :: "r"((uint32_t)(a)) : "memory")
#define MB_WAIT(a, par) do { \
    uint32_t _m = (uint32_t)(a), _p = (uint32_t)(par), _d; \
    asm volatile("{\n\t.reg .pred p;\n\tmbarrier.try_wait.parity.acquire.cta.shared::cta.b64 p, [%1], %2;\n\tselp.b32 %0, 1, 0, p;\n\t}" \
                 : "=r"(_d) : "r"(_m), "r"(_p) : "memory"); \
    if (!_d) asm volatile("{\n\t.reg .pred P1;\n\tWL_%=:\n\tmbarrier.try_wait.parity.acquire.cta.shared::cta.b64 P1, [%0], %1, 0x989680;\n\t@P1 bra.uni WD_%=;\n\tbra.uni WL_%=;\n\tWD_%=:\n\t}" \
                 :: "r"(_m), "r"(_p) : "memory"); \
} while (0)
#define BULK(dst, src, bytes, mb) do { \
    asm volatile("mbarrier.arrive.expect_tx.shared.b64 _, [%0], %1;" :: "r"((uint32_t)(mb)), "r"((uint32_t)(bytes)) : "memory"); \
    asm volatile("cp.async.bulk.shared::cluster.global.mbarrier::complete_tx::bytes [%0], [%1], %2, [%3];" \
                 :: "r"((uint32_t)(dst)), "l"(src), "r"((uint32_t)(bytes)), "r"((uint32_t)(mb)) : "memory"); \
} while (0)

__global__ void detect_idx(const int* ei) {
    int z = 0;
    for (int i = 0; i < 64; i++) z |= ei[2 * i + 1];
    g_idx64 = (z == 0) ? 1 : 0;
}

// ---------- P1 ----------
__global__ void __launch_bounds__(256) prep_nodes(
    const float* __restrict__ z, const float* __restrict__ cell, const float* __restrict__ esm,
    const float* __restrict__ w1, const float* __restrict__ b1,
    const float* __restrict__ w2, const float* __restrict__ b2,
    const float* __restrict__ w3, const float* __restrict__ b3) {
    __shared__ float sc[4][4], h1[4][64], h2[4][32], m16[4][16];
    const int sub = threadIdx.x >> 6, t = threadIdx.x & 63;
    const int i = blockIdx.x * 4 + sub;
    if (t < 4) sc[sub][t] = cell[i * 4 + t];
    __syncthreads();
    {
        float s = b1[t];
        for (int j = 0; j < 4; j++) s += sc[sub][j] * w1[j * 64 + t];
        h1[sub][t] = fmaxf(s, 0.f);
    }
    __syncthreads();
    if (t < 32) {
        float s = b2[t];
        for (int j = 0; j < 64; j++) s += h1[sub][j] * w2[j * 32 + t];
        h2[sub][t] = fmaxf(s, 0.f);
    }
    __syncthreads();
    if (t < 16) {
        float s = b3[t];
        for (int j = 0; j < 32; j++) s += h2[sub][j] * w3[j * 16 + t];
        m16[sub][t] = s;
    }
    __syncthreads();
    for (int col = t; col < KY; col += 64) {
        float v = 0.f;
        if (col < 64)       v = z[i * 64 + col];
        else if (col < 80)  v = m16[sub][col - 64];
        else if (col < 400) v = esm[i * 320 + (col - 80)];
        g_zc[(size_t)i * KY + col] = __float2half_rn(v);
    }
}

// ---------- P2 ----------
__global__ void prep_weights(const float* __restrict__ fw1, const float* __restrict__ fw2,
                             const float* __restrict__ fw3) {
    int i = blockIdx.x * blockDim.x + threadIdx.x;
    const int T1 = 26 * 17920, T2s = 7 * 16384, T3s = 4 * 8192, T2 = 7 * 18432, T3 = 4 * 9216;
    if (i < T1) {
        int chunk = i / 17920, r = i % 17920;
        int h = chunk / 13, c = chunk % 13;
        int n = r / 40, kk = r % 40;
        int k = c * 32 + kk;
        float v = 0.f;
        if (kk < 32 && n < 400 && k < 400) v = fw1[(h * 400 + k) * 400 + n];
        g_w1c[i] = __float2half_rn(v);
    } else if (i < T1 + T2s) {
        int j = i - T1;
        int c = j / 16384, w = j % 16384;
        int nb = w / 4096, b = (w % 4096) * 2;
        uint32_t l = SWZ((uint32_t)b);
        int r = l >> 7, kk = (l & 127) >> 1;
        int n = nb * 64 + r, k = c * 64 + kk;
        g_w2s[j] = __float2half_rn((n < 200 && k < 400) ? fw2[k * 200 + n] : 0.f);
    } else if (i < T1 + T2s + T3s) {
        int j = i - T1 - T2s;
        int c = j / 8192, w = j % 8192;
        int nb = w / 4096, b = (w % 4096) * 2;
        uint32_t l = SWZ((uint32_t)b);
        int r = l >> 7, kk = (l & 127) >> 1;
        int n = nb * 64 + r, k = c * 64 + kk;
        g_w3s[j] = __float2half_rn((n < 100 && k < 200) ? fw3[k * 100 + n] : 0.f);
    } else if (i < T1 + T2s + T3s + T2) {
        int j = i - T1 - T2s - T3s;
        int c = j / 18432, r = j % 18432;
        int n = r / 72, kk = r % 72;
        int k = c * 64 + kk;
        g_w2c[j] = __float2half_rn((kk < 64 && n < 200 && k < 400) ? fw2[k * 200 + n] : 0.f);
    } else if (i < T1 + T2s + T3s + T2 + T3) {
        int j = i - T1 - T2s - T3s - T2;
        int c = j / 9216, r = j % 9216;
        int n = r / 72, kk = r % 72;
        int k = c * 64 + kk;
        g_w3c[j] = __float2half_rn((kk < 64 && n < 100 && k < 200) ? fw3[k * 100 + n] : 0.f);
    }
}

// ---------- gemm32b + prep_y (HMMA, unchanged) ----------
template <int NTILES, int NCH>
__device__ __forceinline__ void gemm32b(const __half* __restrict__ Wc,
                                        const __half* __restrict__ Wnextc,
                                        uint32_t aA, uint32_t aB, int SA, float* acc,
                                        uint32_t mb0, uint32_t mb1, int& icnt, int& wcnt, int* ph,
                                        int wm, int wn, int lane, int tid) {
#pragma unroll
    for (int i = 0; i < 2 * NTILES * 4; i++) acc[i] = 0.f;
    const uint32_t brow = wn * (NTILES * 8) + (lane & 7) + ((lane >> 4) << 3);
#pragma unroll 1
    for (int c = 0; c < NCH; c++) {
        const __half* nsrc = (c + 1 < NCH) ? Wc + (size_t)(c + 1) * 17920 : Wnextc;
        if (nsrc && tid == 0) {
            int buf = icnt & 1;
            BULK(aB + buf * BS32BYTES, nsrc, BS32BYTES, buf ? mb1 : mb0);
        }
        if (nsrc) icnt++;
        int buf = wcnt & 1;
        MB_WAIT(buf ? mb1 : mb0, ph[buf]);
        ph[buf] ^= 1;
        wcnt++;
        const uint32_t bbase = aB + buf * BS32BYTES;
#pragma unroll
        for (int s = 0; s < 2; s++) {
            uint32_t aaddr = aA + (((wm * 32 + (lane & 15)) * SA + c * 32 + s * 16 + ((lane >> 4) << 3)) << 1);
            uint32_t a0, a1, a2, a3, e0, e1, e2, e3;
            LDSM4(a0, a1, a2, a3, aaddr);
            LDSM4(e0, e1, e2, e3, aaddr + 16 * SA * 2);
            uint32_t baddr = bbase + ((brow * SBS32 + s * 16 + (((lane >> 3) & 1) << 3)) << 1);
#pragma unroll
            for (int g = 0; g < NTILES / 2; g++) {
                uint32_t b0, b1, b2, b3;
                LDSM4(b0, b1, b2, b3, baddr + g * (16 * SBS32 * 2));
                HMMA(acc + (2 * g) * 4, a0, a1, a2, a3, b0, b1);
                HMMA(acc + (2 * g + 1) * 4, a0, a1, a2, a3, b2, b3);
                HMMA(acc + (NTILES + 2 * g) * 4, e0, e1, e2, e3, b0, b1);
                HMMA(acc + (NTILES + 2 * g + 1) * 4, e0, e1, e2, e3, b2, b3);
            }
            if (NTILES & 1) {
                uint32_t b0, b1;
                LDSM2(b0, b1, baddr + (NTILES / 2) * (16 * SBS32 * 2));
                HMMA(acc + (NTILES - 1) * 4, a0, a1, a2, a3, b0, b1);
                HMMA(acc + (2 * NTILES - 1) * 4, e0, e1, e2, e3, b0, b1);
            }
        }
        __syncthreads();
    }
}

#define SMY_MB 0
#define SMY_A  64
#define SMY_B  (64 + 54272)
#define SMEM_Y (SMY_B + 2 * BS32BYTES)

__global__ void __launch_bounds__(512) prep_y_kernel() {
    extern __shared__ char smem[];
    const uint32_t mb0 = smem_u32(smem + SMY_MB);
    const uint32_t mb1 = mb0 + 8;
    const uint32_t aA = smem_u32(smem + SMY_A);
    const uint32_t aB = smem_u32(smem + SMY_B);
    const int tid = threadIdx.x;
    const int wid = tid >> 5, lane = tid & 31;
    const int wm = wid & 1, wn = wid >> 1;
    const int base = blockIdx.x * 64;

    if (tid == 0) { MB_INIT(mb0, 1); MB_INIT(mb1, 1); }
    __syncthreads();
    int icnt = 0, wcnt = 0, ph[2] = {0, 0};
    if (tid == 0) BULK(aB, g_w1c, BS32BYTES, mb0);
    icnt++;
    for (int i = tid; i < 64 * 52; i += 512) {
        int r = i / 52, u = i % 52;
        int grow = base + r; if (grow > 19999) grow = 19999;
        CPA16(aA + ((r * SA_Y + u * 8) << 1), g_zc + (size_t)grow * KY + u * 8);
    }
    CPA_COMMIT(); CPA_WAIT(0);
    __syncthreads();

    float acc[56];
    gemm32b<7, 13>(g_w1c, g_w1c + (size_t)13 * 17920, aA, aB, SA_Y, acc, mb0, mb1, icnt, wcnt, ph, wm, wn, lane, tid);
#pragma unroll
    for (int mt = 0; mt < 2; mt++) {
        int r0 = base + wm * 32 + mt * 16 + (lane >> 2);
#pragma unroll
        for (int nt = 0; nt < 7; nt++) {
            int c = wn * 56 + nt * 8 + (lane & 3) * 2;
            float* d = acc + (mt * 7 + nt) * 4;
            if (r0 < 20000) *(__half2*)(g_ytop + (size_t)r0 * N1 + c) = __floats2half2_rn(d[0], d[1]);
            if (r0 + 8 < 20000) *(__half2*)(g_ytop + (size_t)(r0 + 8) * N1 + c) = __floats2half2_rn(d[2], d[3]);
        }
    }
    gemm32b<7, 13>(g_w1c + (size_t)13 * 17920, nullptr, aA, aB, SA_Y, acc, mb0, mb1, icnt, wcnt, ph, wm, wn, lane, tid);
#pragma unroll
    for (int mt = 0; mt < 2; mt++) {
        int r0 = base + wm * 32 + mt * 16 + (lane >> 2);
#pragma unroll
        for (int nt = 0; nt < 7; nt++) {
            int c = wn * 56 + nt * 8 + (lane & 3) * 2;
            float* d = acc + (mt * 7 + nt) * 4;
            if (r0 < 20000) *(__half2*)(g_ybot + (size_t)r0 * N1 + c) = __floats2half2_rn(d[0], d[1]);
            if (r0 + 8 < 20000) *(__half2*)(g_ybot + (size_t)(r0 + 8) * N1 + c) = __floats2half2_rn(d[2], d[3]);
        }
    }
}

// ---------- tcgen05 edge kernel ----------
#define SMT_TM   0
#define SMT_MB   8          // full0 8, full1 16, free0 24, free1 32, done 40
#define SMT_NS   64
#define SMT_ND   576
#define SMT_BIAS 1088
#define SMT_ACT  5120       // 7 x 16384
#define SMT_B    119808     // 2 x 32768
#define SMEM_T   185344
#define ID64 ((1u << 4) | (8u << 17) | (8u << 24))
static constexpr uint64_t DBASE =
    (uint64_t(2) << 61) | (uint64_t(1) << 46) | (uint64_t(64) << 32) | (uint64_t(1) << 16);
__device__ __forceinline__ uint64_t make_desc(uint32_t a) { return DBASE | ((uint64_t)(a >> 4) & 0x3FFF); }

#if defined(__CUDA_ARCH_FEAT_SM103_ALL) || defined(__CUDA_ARCH_FEAT_SM100_ALL)
#define TC_OK 1
#define TC_ALLOC(sa, n)  asm volatile("tcgen05.alloc.cta_group::1.sync.aligned.shared::cta.b32 [%0], %1;" :: "r"((uint32_t)(sa)), "r"((uint32_t)(n)) : "memory")
#define TC_DEALLOC(t, n) asm volatile("tcgen05.dealloc.cta_group::1.sync.aligned.b32 %0, %1;" :: "r"(t), "r"((uint32_t)(n)))
#define TC_COMMIT(mb)    asm volatile("tcgen05.commit.cta_group::1.mbarrier::arrive::one.shared::cluster.b64 [%0];" :: "r"((uint32_t)(mb)) : "memory")
#define TC_WAIT_LD()     asm volatile("tcgen05.wait::ld.sync.aligned;" ::: "memory")
#define TC_FA()          asm volatile("tcgen05.fence::after_thread_sync;" ::: "memory")
#define TC_FB()          asm volatile("tcgen05.fence::before_thread_sync;" ::: "memory")
#define FENCE_ASYNC()    asm volatile("fence.proxy.async.shared::cta;" ::: "memory")
#define TCMMA(d, ad, bd, en) \
    asm volatile("{\n\t.reg .pred p;\n\tsetp.ne.u32 p, %5, 0;\n\t" \
                 "tcgen05.mma.cta_group::1.kind::f16 [%0], %1, %2, %3, {%4, %4, %4, %4}, p;\n\t}" \
                 :: "r"(d), "l"(ad), "l"(bd), "r"(ID64), "r"(0u), "r"((uint32_t)(en)) : "memory")
#define TC_LD32(r, a) \
    asm volatile("tcgen05.ld.sync.aligned.32x32b.x32.b32 " \
        "{%0,%1,%2,%3,%4,%5,%6,%7,%8,%9,%10,%11,%12,%13,%14,%15," \
        "%16,%17,%18,%19,%20,%21,%22,%23,%24,%25,%26,%27,%28,%29,%30,%31}, [%32];" \
        : "=r"((r)[0]),"=r"((r)[1]),"=r"((r)[2]),"=r"((r)[3]),"=r"((r)[4]),"=r"((r)[5]),"=r"((r)[6]),"=r"((r)[7]), \
          "=r"((r)[8]),"=r"((r)[9]),"=r"((r)[10]),"=r"((r)[11]),"=r"((r)[12]),"=r"((r)[13]),"=r"((r)[14]),"=r"((r)[15]), \
          "=r"((r)[16]),"=r"((r)[17]),"=r"((r)[18]),"=r"((r)[19]),"=r"((r)[20]),"=r"((r)[21]),"=r"((r)[22]),"=r"((r)[23]), \
          "=r"((r)[24]),"=r"((r)[25]),"=r"((r)[26]),"=r"((r)[27]),"=r"((r)[28]),"=r"((r)[29]),"=r"((r)[30]),"=r"((r)[31]) \
        : "r"(a))
#endif

__global__ void __cluster_dims__(1, 1, 1) __launch_bounds__(512) edge_tc_kernel(
    const void* __restrict__ eidx_raw, const float* __restrict__ fb1,
    const float* __restrict__ fb2, const float* __restrict__ fb3,
    const float* __restrict__ fw4, const float* __restrict__ fb4,
    float* __restrict__ out) {
    extern __shared__ char smem[];
    const int tid = threadIdx.x;
    const int wid = tid >> 5, lane = tid & 31;
    const long long base = (long long)blockIdx.x * 128;
    int* ns = (int*)(smem + SMT_NS);
    int* nd = (int*)(smem + SMT_ND);
    float* bias = (float*)(smem + SMT_BIAS);

    for (int i = tid; i < 448; i += 512) bias[i] = (i < 400) ? fb1[i] : 0.f;
    if (tid < 256) bias[448 + tid] = (tid < 200) ? fb2[tid] : 0.f;
    else if (tid < 384) { int i = tid - 256; bias[704 + i] = (i < 100) ? fb3[i] : 0.f; }
    else { int i = tid - 384; bias[832 + i] = (i < 100) ? fw4[i] : 0.f; }
    if (tid == 0) bias[960] = fb4[0];
    if (tid < 128) {
        long long e = base + tid;
        if (e >= N_EDGES_C) e = N_EDGES_C - 1;
        if (g_idx64) {
            const long long* ei = (const long long*)eidx_raw;
            ns[tid] = (int)ei[e]; nd[tid] = (int)ei[N_EDGES_C + e];
        } else {
            const int* ei = (const int*)eidx_raw;
            ns[tid] = ei[e]; nd[tid] = ei[N_EDGES_C + e];
        }
    }
#ifdef TC_OK
    const uint32_t sb = smem_u32(smem);
    const uint32_t mbF0 = sb + 8, mbF1 = sb + 16, mbE0 = sb + 24, mbE1 = sb + 32, mbD = sb + 40;
    if (tid == 0) { MB_INIT(mbF0, 1); MB_INIT(mbF1, 1); MB_INIT(mbE0, 1); MB_INIT(mbE1, 1); MB_INIT(mbD, 1); }
    if (tid < 32) TC_ALLOC(sb + SMT_TM, 512);
    __syncthreads();
    uint32_t tmem;
    asm volatile("ld.shared.b32 %0, [%1];" : "=r"(tmem) : "r"(sb + SMT_TM));

    // pipeline state (tid0 only)
    int phF[2] = {0, 0}, phE[2] = {0, 0}, pend[2] = {0, 0};
#define TFILL(buf, src, bytes) do { \
    if (pend[buf]) { MB_WAIT((buf) ? mbE1 : mbE0, phE[buf]); phE[buf] ^= 1; pend[buf] = 0; } \
    BULK(sb + SMT_B + (buf) * 32768, src, bytes, (buf) ? mbF1 : mbF0); } while (0)
#define TWAITF(buf) do { MB_WAIT((buf) ? mbF1 : mbF0, phF[buf]); phF[buf] ^= 1; } while (0)

    if (tid == 0) TFILL(0, g_w2s, 32768);

    // combine: act1 chunks SW128
    for (int i = tid; i < 7168; i += 512) {
        int ch = i >> 10, rem = i & 1023, r = rem >> 3, ug = rem & 7;
        int col = ch * 64 + ug * 8;
        uint4 tv = *(const uint4*)(g_ytop + (size_t)ns[r] * N1 + col);
        uint4 bv = *(const uint4*)(g_ybot + (size_t)nd[r] * N1 + col);
        const __half2* tp = (const __half2*)&tv;
        const __half2* bp = (const __half2*)&bv;
        __half2 h[4];
#pragma unroll
        for (int j = 0; j < 4; j++) {
            float2 t2 = __half22float2(tp[j]);
            float2 b2 = __half22float2(bp[j]);
            h[j] = __floats2half2_rn(fmaxf(t2.x + b2.x + bias[col + 2 * j], 0.f),
                                     fmaxf(t2.y + b2.y + bias[col + 2 * j + 1], 0.f));
        }
        *(uint4*)(smem + SMT_ACT + ch * 16384 + SWZ((uint32_t)(r * 128 + ug * 16))) = *(uint4*)h;
    }
    FENCE_ASYNC();
    __syncthreads();

    // FC2 master (tid0): D cols 0..255
    if (tid == 0) {
        for (int c = 0; c < 7; c++) {
            int buf = c & 1;
            if (c + 1 < 7) TFILL((c + 1) & 1, g_w2s + (size_t)(c + 1) * 16384, 32768);
            TWAITF(buf);
            uint64_t ad = make_desc(sb + SMT_ACT + c * 16384);
#pragma unroll
            for (int nb = 0; nb < 4; nb++) {
                uint64_t bd = make_desc(sb + SMT_B + buf * 32768 + nb * 8192);
#pragma unroll
                for (int ks = 0; ks < 4; ks++)
                    TCMMA(tmem + nb * 64, ad + ks * 2, bd + ks * 2, !(c == 0 && ks == 0));
            }
            TC_COMMIT(buf ? mbE1 : mbE0);
            pend[buf] = 1;
        }
        MB_WAIT(mbE0, phE[0]); phE[0] ^= 1; pend[0] = 0;   // chunk6 MMAs done
        TFILL(0, g_w3s, 16384);
        TFILL(1, g_w3s + 8192, 16384);
        MB_ARRIVE(mbD);
    }
    MB_WAIT(mbD, 0);
    TC_FA();

    // epilogue1: act2 = relu(D+b2) f16 -> chunks 0..3
    {
        int sub = wid & 3, cg = wid >> 2;
        int row = sub * 32 + lane;
#pragma unroll 1
        for (int bi = 0; bi < 2; bi++) {
            uint32_t r[32];
            TC_LD32(r, tmem + cg * 64 + bi * 32);
            TC_WAIT_LD();
#pragma unroll
            for (int j4 = 0; j4 < 4; j4++) {
                __half2 h[4];
#pragma unroll
                for (int p = 0; p < 4; p++) {
                    int cc = j4 * 8 + p * 2;
                    int col = cg * 64 + bi * 32 + cc;
                    h[p] = __floats2half2_rn(fmaxf(__uint_as_float(r[cc]) + bias[448 + col], 0.f),
                                             fmaxf(__uint_as_float(r[cc + 1]) + bias[448 + col + 1], 0.f));
                }
                *(uint4*)(smem + SMT_ACT + cg * 16384 + SWZ((uint32_t)(row * 128 + bi * 64 + j4 * 16))) = *(uint4*)h;
            }
        }
        TC_FB();
    }
    FENCE_ASYNC();
    __syncthreads();

    // FC3 master: D cols 256..383
    if (tid == 0) {
        for (int c = 0; c < 4; c++) {
            int buf = c & 1;
            TWAITF(buf);
            uint64_t ad = make_desc(sb + SMT_ACT + c * 16384);
#pragma unroll
            for (int nb = 0; nb < 2; nb++) {
                uint64_t bd = make_desc(sb + SMT_B + buf * 32768 + nb * 8192);
#pragma unroll
                for (int ks = 0; ks < 4; ks++)
                    TCMMA(tmem + 256 + nb * 64, ad + ks * 2, bd + ks * 2, !(c == 0 && ks == 0));
            }
            TC_COMMIT(buf ? mbE1 : mbE0);
            pend[buf] = 1;
            if (c + 2 < 4) TFILL(buf, g_w3s + (size_t)(c + 2) * 8192, 16384);
        }
        MB_WAIT(mbE1, phE[1]); phE[1] ^= 1; pend[1] = 0;   // chunk3 done (in-order => all done)
        MB_ARRIVE(mbD);
    }
    MB_WAIT(mbD, 1);
    TC_FA();

    // head (warps 0..3)
    if (wid < 4) {
        float s = bias[960];
#pragma unroll 1
        for (int b = 0; b < 4; b++) {
            uint32_t r[32];
            TC_LD32(r, tmem + 256 + b * 32);
            TC_WAIT_LD();
#pragma unroll
            for (int j = 0; j < 32; j++) {
                int col = b * 32 + j;
                if (col < 100)
                    s += fmaxf(__uint_as_float(r[j]) + bias[704 + col], 0.f) * bias[832 + col];
            }
        }
        TC_FB();
        long long e = base + wid * 32 + lane;
        if (e < N_EDGES_C) out[e] = s;
    }
    __syncthreads();
    if (tid < 32) TC_DEALLOC(tmem, 512);
#else
    // fallback (base target; not expected to run): warp-per-edge scalar
    __syncthreads();
    __shared__ float a1[16][448];
    __shared__ float a2[16][256];
    for (int q = wid; q < 128; q += 16) {
        long long e = base + q;
        if (e >= N_EDGES_C) break;
        for (int i = lane; i < 448; i += 32)
            a1[wid][i] = fmaxf(__half2float(g_ytop[(size_t)ns[q] * N1 + i]) +
                               __half2float(g_ybot[(size_t)nd[q] * N1 + i]) + bias[i], 0.f);
        __syncwarp();
        for (int n = lane; n < 256; n += 32) {
            float s = 0.f;
            for (int c = 0; c < 7; c++)
                for (int kk = 0; kk < 64; kk++)
                    s += a1[wid][c * 64 + kk] * __half2float(g_w2c[(size_t)c * 18432 + n * 72 + kk]);
            a2[wid][n] = fmaxf(s + bias[448 + n], 0.f);
        }
        __syncwarp();
        float s = 0.f;
        for (int n = lane; n < 128; n += 32) {
            float t = 0.f;
            for (int c = 0; c < 4; c++)
                for (int kk = 0; kk < 64; kk++)
                    t += a2[wid][c * 64 + kk] * __half2float(g_w3c[(size_t)c * 9216 + n * 72 + kk]);
            s += fmaxf(t + bias[704 + n], 0.f) * bias[832 + n];
        }
        for (int o = 16; o; o >>= 1) s += __shfl_xor_sync(~0u, s, o);
        if (lane == 0) out[e] = s + bias[960];
        __syncwarp();
    }
#endif
}

extern "C" void kernel_launch(void* const* d_in, const int* in_sizes, int n_in,
                              void* d_out, int out_size) {
    static const int EXP[18] = {1280000, 1000000, 80000, 6400000, 256, 64, 2048, 32, 512, 16,
                                320000, 400, 80000, 200, 20000, 100, 100, 1};
    const void* p[18];
    bool used[32] = {false};
    for (int j = 0; j < 18; j++) {
        p[j] = (j < n_in) ? d_in[j] : nullptr;
        for (int i = 0; i < n_in && i < 32; i++) {
            if (!used[i] && in_sizes[i] == EXP[j]) { p[j] = d_in[i]; used[i] = true; break; }
        }
    }
    const float* z    = (const float*)p[0];
    const void*  ei   = p[1];
    const float* cell = (const float*)p[2];
    const float* esm  = (const float*)p[3];
    const float* mw1 = (const float*)p[4];
    const float* mb1 = (const float*)p[5];
    const float* mw2 = (const float*)p[6];
    const float* mb2 = (const float*)p[7];
    const float* mw3 = (const float*)p[8];
    const float* mb3 = (const float*)p[9];
    const float* f1w = (const float*)p[10];
    const float* f1b = (const float*)p[11];
    const float* f2w = (const float*)p[12];
    const float* f2b = (const float*)p[13];
    const float* f3w = (const float*)p[14];
    const float* f3b = (const float*)p[15];
    const float* f4w = (const float*)p[16];
    const float* f4b = (const float*)p[17];
    float* out = (float*)d_out;

    cudaFuncSetAttribute(prep_y_kernel, cudaFuncAttributeMaxDynamicSharedMemorySize, SMEM_Y);
    cudaFuncSetAttribute(edge_tc_kernel, cudaFuncAttributeMaxDynamicSharedMemorySize, SMEM_T);

    detect_idx<<<1, 1>>>((const int*)ei);
    prep_nodes<<<5000, 256>>>(z, cell, esm, mw1, mb1, mw2, mb2, mw3, mb3);
    const int WT = 26 * 17920 + 7 * 16384 + 4 * 8192 + 7 * 18432 + 4 * 9216;
    prep_weights<<<(WT + 255) / 256, 256>>>(f1w, f2w, f3w);
    prep_y_kernel<<<313, 512, SMEM_Y>>>();
    edge_tc_kernel<<<(N_EDGES_C + 127) / 128, 512, SMEM_T>>>(
        ei, f1b, f2b, f3b, f4w, f4b, out);
}